// round 7
// baseline (speedup 1.0000x reference)
#include <cuda_runtime.h>
#include <cuda_bf16.h>
#include <stdint.h>

// Problem constants
#define BATCH   128
#define TSTEPS  512
#define DIN     512
#define DOUT    512
#define MROWS   (BATCH * TSTEPS)        // 65536
#define BETA    0.95f
#define THRESH  1.0f
#define FLAG_EPS 2e-3f

// GEMM tiling
#define BM 128
#define BN 128
#define KC 32
#define NCHUNK (DIN / KC)               // 16
#define SRW 20                          // smem row stride in words (16 data + 4 pad)
#define SUBW (128 * SRW)                // 2560 words per sub-tile
#define STAGEW (4 * SUBW)               // A0 A1 B0 B1
#define SMEM_BYTES (2 * STAGEW * 4)     // 81920

// Persistent scratch (static device globals)
__device__ float g_currents[(size_t)MROWS * DOUT];                 // 128 MB
__device__ __nv_bfloat16 g_A0[(size_t)MROWS * DIN];                // 64 MB
__device__ __nv_bfloat16 g_A1[(size_t)MROWS * DIN];                // 64 MB
__device__ __nv_bfloat16 g_W0[(size_t)DOUT * DIN];
__device__ __nv_bfloat16 g_W1[(size_t)DOUT * DIN];
__device__ unsigned long long g_spike_count;
__device__ int g_bcount[BATCH];                  // flagged-lane count per batch
__device__ int g_bflag_d[BATCH * DOUT];          // flagged d list per batch

// ---------------------------------------------------------------------------
__global__ void zero_kernel() {
    if (threadIdx.x == 0) g_spike_count = 0ull;
    if (threadIdx.x < BATCH) g_bcount[threadIdx.x] = 0;
}

// ---------------------------------------------------------------------------
// 2-way bf16 split: x = b0 + b1 + O(2^-18 x)
// ---------------------------------------------------------------------------
__global__ __launch_bounds__(256)
void split2_kernel(const float4* __restrict__ src,
                   uint2* __restrict__ o0, uint2* __restrict__ o1, int n4)
{
    int i = blockIdx.x * blockDim.x + threadIdx.x;
    if (i >= n4) return;
    float4 v = src[i];
    float f[4] = {v.x, v.y, v.z, v.w};
    uint16_t h0[4], h1[4];
#pragma unroll
    for (int j = 0; j < 4; j++) {
        __nv_bfloat16 b0 = __float2bfloat16(f[j]);
        __nv_bfloat16 b1 = __float2bfloat16(f[j] - __bfloat162float(b0));
        h0[j] = __bfloat16_as_ushort(b0);
        h1[j] = __bfloat16_as_ushort(b1);
    }
    uint2 p0, p1;
    p0.x = ((uint32_t)h0[1] << 16) | h0[0];
    p0.y = ((uint32_t)h0[3] << 16) | h0[2];
    p1.x = ((uint32_t)h1[1] << 16) | h1[0];
    p1.y = ((uint32_t)h1[3] << 16) | h1[2];
    o0[i] = p0;
    o1[i] = p1;
}

// ---------------------------------------------------------------------------
// cp.async + mma helpers (sm_80 baseline PTX)
// ---------------------------------------------------------------------------
__device__ __forceinline__ uint32_t smem_u32(const void* p) {
    uint32_t a;
    asm("{ .reg .u64 t; cvta.to.shared.u64 t, %1; cvt.u32.u64 %0, t; }" : "=r"(a) : "l"(p));
    return a;
}
#define CP_ASYNC16(dst_u32, src_ptr) \
    asm volatile("cp.async.cg.shared.global [%0], [%1], 16;" :: "r"(dst_u32), "l"(src_ptr) : "memory")
#define CP_COMMIT() asm volatile("cp.async.commit_group;" ::: "memory")
#define CP_WAIT1()  asm volatile("cp.async.wait_group 1;" ::: "memory")
#define CP_WAIT0()  asm volatile("cp.async.wait_group 0;" ::: "memory")

__device__ __forceinline__ void mma_bf16(float* d, const uint32_t* a, const uint32_t* b) {
    asm volatile(
        "mma.sync.aligned.m16n8k16.row.col.f32.bf16.bf16.f32 "
        "{%0,%1,%2,%3}, {%4,%5,%6,%7}, {%8,%9}, {%0,%1,%2,%3};"
        : "+f"(d[0]), "+f"(d[1]), "+f"(d[2]), "+f"(d[3])
        : "r"(a[0]), "r"(a[1]), "r"(a[2]), "r"(a[3]), "r"(b[0]), "r"(b[1]));
}

// ---------------------------------------------------------------------------
// bf16x4 approx GEMM: C[m,n] = sum_k A[m,k]*W[n,k] + bias[n]  (err ~1e-6)
// ---------------------------------------------------------------------------
__global__ __launch_bounds__(256, 1)
void gemm_bf16x4_kernel(const __nv_bfloat16* __restrict__ A0,
                        const __nv_bfloat16* __restrict__ A1,
                        const __nv_bfloat16* __restrict__ B0,
                        const __nv_bfloat16* __restrict__ B1,
                        const float* __restrict__ bias,
                        float* __restrict__ C)
{
    extern __shared__ uint32_t smw[];
    const int tid  = threadIdx.x;
    const int wid  = tid >> 5;
    const int lane = tid & 31;
    const int wm = wid & 1;
    const int wn = wid >> 1;
    const int rowBase = blockIdx.y * BM;
    const int colBase = blockIdx.x * BN;
    const int q  = lane >> 2;
    const int tg = lane & 3;

    const uint32_t sb = smem_u32(smw);
    const __nv_bfloat16* Asrc[2] = {A0, A1};
    const __nv_bfloat16* Bsrc[2] = {B0, B1};

    float acc[4][4][4];
#pragma unroll
    for (int an = 0; an < 4; an++) {
        int c0 = colBase + wn * 32 + an * 8 + tg * 2;
        float b0 = __ldg(bias + c0), b1 = __ldg(bias + c0 + 1);
#pragma unroll
        for (int am = 0; am < 4; am++) {
            acc[am][an][0] = b0; acc[am][an][1] = b1;
            acc[am][an][2] = b0; acc[am][an][3] = b1;
        }
    }

    auto issue_chunk = [&](int j) {
        const uint32_t st = sb + (uint32_t)((j & 1) * STAGEW) * 4u;
        const int k0 = j * KC;
#pragma unroll
        for (int l = 0; l < 8; l++) {
            int idx = tid + l * 256;       // 0..2047
            int sub = idx >> 9;            // 0..3
            int t = idx & 511;
            int r = t >> 2;
            int c16 = t & 3;
            uint32_t doff = (uint32_t)(sub * SUBW + r * SRW + c16 * 4) * 4u;
            const __nv_bfloat16* src = (sub < 2)
                ? Asrc[sub] + (size_t)(rowBase + r) * DIN + k0 + c16 * 8
                : Bsrc[sub - 2] + (size_t)(colBase + r) * DIN + k0 + c16 * 8;
            CP_ASYNC16(st + doff, src);
        }
        CP_COMMIT();
    };

    issue_chunk(0);

    const int aRow = wm * 64 + q;
    const int bRow = wn * 32 + q;

    for (int j = 0; j < NCHUNK; j++) {
        if (j + 1 < NCHUNK) { issue_chunk(j + 1); CP_WAIT1(); }
        else                { CP_WAIT0(); }
        __syncthreads();

        const uint32_t* st = smw + (j & 1) * STAGEW;
        const uint32_t* sA = st;
        const uint32_t* sB = st + 2 * SUBW;

#pragma unroll
        for (int s = 0; s < 2; s++) {
            const int kb = s * 8 + tg;
            uint32_t af[2][4][4];
#pragma unroll
            for (int am = 0; am < 4; am++) {
                int r0 = (aRow + am * 16) * SRW + kb;
                int r1 = r0 + 8 * SRW;
#pragma unroll
                for (int p = 0; p < 2; p++) {
                    const uint32_t* a = sA + p * SUBW;
                    af[p][am][0] = a[r0];
                    af[p][am][1] = a[r1];
                    af[p][am][2] = a[r0 + 4];
                    af[p][am][3] = a[r1 + 4];
                }
            }
            uint32_t bf[2][4][2];
#pragma unroll
            for (int an = 0; an < 4; an++) {
                int rb = (bRow + an * 8) * SRW + kb;
#pragma unroll
                for (int p = 0; p < 2; p++) {
                    const uint32_t* b = sB + p * SUBW;
                    bf[p][an][0] = b[rb];
                    bf[p][an][1] = b[rb + 4];
                }
            }
#pragma unroll
            for (int am = 0; am < 4; am++)
#pragma unroll
                for (int an = 0; an < 4; an++) {
                    float* d = acc[am][an];
                    mma_bf16(d, af[1][am], bf[1][an]);
                    mma_bf16(d, af[1][am], bf[0][an]);
                    mma_bf16(d, af[0][am], bf[1][an]);
                    mma_bf16(d, af[0][am], bf[0][an]);
                }
        }
        __syncthreads();
    }

#pragma unroll
    for (int am = 0; am < 4; am++) {
        int r0 = rowBase + wm * 64 + am * 16 + q;
#pragma unroll
        for (int an = 0; an < 4; an++) {
            int c = colBase + wn * 32 + an * 8 + tg * 2;
            *(float2*)(C + (size_t)r0 * DOUT + c)       = make_float2(acc[am][an][0], acc[am][an][1]);
            *(float2*)(C + (size_t)(r0 + 8) * DOUT + c) = make_float2(acc[am][an][2], acc[am][an][3]);
        }
    }
}

// ---------------------------------------------------------------------------
// LIF flag scan: approx scan; flag lanes with any |mem-1| < FLAG_EPS.
// Counts spikes only for unflagged lanes; flagged lanes queued for fixup.
// ---------------------------------------------------------------------------
__global__ __launch_bounds__(256)
void lif_flag_scan_kernel(const float* __restrict__ cur,
                          float* __restrict__ spikes)
{
    const int idx = blockIdx.x * blockDim.x + threadIdx.x;
    const int b = idx >> 9;
    const int d = idx & (DOUT - 1);

    const float* cp = cur    + (size_t)b * TSTEPS * DOUT + d;
    float*       sp = spikes + (size_t)b * TSTEPS * DOUT + d;

    float mem = 0.0f;
    int cnt = 0;
    int flagged = 0;
#pragma unroll 8
    for (int t = 0; t < TSTEPS; t++) {
        float c = cp[(size_t)t * DOUT];
        mem = fmaf(BETA, mem, c);
        flagged |= (fabsf(mem - THRESH) < FLAG_EPS) ? 1 : 0;
        float spk = (mem > THRESH) ? 1.0f : 0.0f;
        mem -= spk * THRESH;
        sp[(size_t)t * DOUT] = spk;
        cnt += (spk > 0.0f) ? 1 : 0;
    }

    if (flagged) {
        cnt = 0;                                  // counted later, exactly
        int slot = atomicAdd(&g_bcount[b], 1);
        g_bflag_d[b * DOUT + slot] = d;
    }

#pragma unroll
    for (int off = 16; off > 0; off >>= 1)
        cnt += __shfl_down_sync(0xffffffffu, cnt, off);
    if ((threadIdx.x & 31) == 0 && cnt > 0)
        atomicAdd(&g_spike_count, (unsigned long long)cnt);
}

// ---------------------------------------------------------------------------
// Fixup phase A: exact fp32-chain currents for flagged lanes.
// Block = (t-tile, b). 256 threads = 32 t-slots x 8 d-slots, thread tile 4t x 4d.
// k ascending fmaf chain + bias at end — bit-identical to the round-1 kernel.
// ---------------------------------------------------------------------------
#define XS_STRIDE 36
__global__ __launch_bounds__(256)
void fix_currents_kernel(const float* __restrict__ x,
                         const float* __restrict__ Wm,
                         const float* __restrict__ bias,
                         float* __restrict__ C)
{
    const int b  = blockIdx.y;
    const int t0 = blockIdx.x * 128;
    const int nd = g_bcount[b];
    if (nd == 0) return;

    __shared__ float xs[128 * XS_STRIDE];    // 18 KB
    __shared__ float ws[32 * XS_STRIDE];     // 4.5 KB
    __shared__ int   dlist[32];

    const int tid = threadIdx.x;
    const int ts = tid >> 3;       // 0..31 -> t rows ts*4 + i
    const int ds = tid & 7;        // 0..7  -> d cols ds*4 + jj

    for (int dc = 0; dc < nd; dc += 32) {
        __syncthreads();
        if (tid < 32) {
            int j = dc + tid;
            dlist[tid] = g_bflag_d[b * DOUT + ((j < nd) ? j : (nd - 1))];
        }

        float acc[4][4];
#pragma unroll
        for (int i = 0; i < 4; i++)
#pragma unroll
            for (int jj = 0; jj < 4; jj++) acc[i][jj] = 0.0f;

        for (int k0 = 0; k0 < DIN; k0 += 32) {
            __syncthreads();
            // stage x tile: 128 t-rows x 32 k (float4 loads, 4/thread)
#pragma unroll
            for (int l = 0; l < 4; l++) {
                int idx = tid + l * 256;          // 0..1023
                int r = idx >> 3, c4 = idx & 7;
                float4 v = *(const float4*)(x + ((size_t)b * TSTEPS + t0 + r) * DIN + k0 + c4 * 4);
                *(float4*)(xs + r * XS_STRIDE + c4 * 4) = v;
            }
            // stage W rows for the 32 flagged d's (1 float4/thread)
            {
                int r = tid >> 3, c4 = tid & 7;   // 32 rows x 8
                float4 v = *(const float4*)(Wm + (size_t)dlist[r] * DIN + k0 + c4 * 4);
                *(float4*)(ws + r * XS_STRIDE + c4 * 4) = v;
            }
            __syncthreads();

            // exact chain: k ascending
            for (int k = 0; k < 32; k++) {
                float wv[4], xv[4];
#pragma unroll
                for (int jj = 0; jj < 4; jj++) wv[jj] = ws[(ds * 4 + jj) * XS_STRIDE + k];
#pragma unroll
                for (int i = 0; i < 4; i++) xv[i] = xs[(ts * 4 + i) * XS_STRIDE + k];
#pragma unroll
                for (int i = 0; i < 4; i++)
#pragma unroll
                    for (int jj = 0; jj < 4; jj++)
                        acc[i][jj] = fmaf(xv[i], wv[jj], acc[i][jj]);
            }
        }

        // write exact currents (+bias, at end — matches reference order)
#pragma unroll
        for (int jj = 0; jj < 4; jj++) {
            int j = dc + ds * 4 + jj;
            if (j < nd) {
                int d = dlist[ds * 4 + jj];
                float bv = bias[d];
#pragma unroll
                for (int i = 0; i < 4; i++) {
                    int t = t0 + ts * 4 + i;
                    C[((size_t)b * TSTEPS + t) * DOUT + d] = acc[i][jj] + bv;
                }
            }
        }
    }
}

// ---------------------------------------------------------------------------
// Fixup phase B: exact rescan of flagged lanes; overwrite spikes, add counts.
// ---------------------------------------------------------------------------
__global__ __launch_bounds__(256)
void fix_scan_kernel(const float* __restrict__ cur,
                     float* __restrict__ spikes)
{
    const int b = blockIdx.x;
    const int nd = g_bcount[b];

    for (int slot = threadIdx.x; slot < nd; slot += blockDim.x) {
        const int d = g_bflag_d[b * DOUT + slot];
        const float* cp = cur    + (size_t)b * TSTEPS * DOUT + d;
        float*       sp = spikes + (size_t)b * TSTEPS * DOUT + d;

        float mem = 0.0f;
        int cnt = 0;
        for (int t = 0; t < TSTEPS; t++) {
            float c = cp[(size_t)t * DOUT];
            mem = fmaf(BETA, mem, c);
            float spk = (mem > THRESH) ? 1.0f : 0.0f;
            mem -= spk * THRESH;
            sp[(size_t)t * DOUT] = spk;
            cnt += (spk > 0.0f) ? 1 : 0;
        }
        atomicAdd(&g_spike_count, (unsigned long long)cnt);
    }
}

__global__ void write_sum_kernel(float* __restrict__ out, int sum_idx) {
    out[sum_idx] = (float)g_spike_count;
}

// ---------------------------------------------------------------------------
extern "C" void kernel_launch(void* const* d_in, const int* in_sizes, int n_in,
                              void* d_out, int out_size)
{
    const float* x    = (const float*)d_in[0];   // [B, T, DIN]
    const float* Wm   = (const float*)d_in[1];   // [DOUT, DIN]
    const float* bias = (const float*)d_in[2];   // [DOUT]
    float* out = (float*)d_out;

    float* currents;
    __nv_bfloat16 *A0, *A1, *W0, *W1;
    cudaGetSymbolAddress((void**)&currents, g_currents);
    cudaGetSymbolAddress((void**)&A0, g_A0);
    cudaGetSymbolAddress((void**)&A1, g_A1);
    cudaGetSymbolAddress((void**)&W0, g_W0);
    cudaGetSymbolAddress((void**)&W1, g_W1);

    cudaFuncSetAttribute(gemm_bf16x4_kernel,
                         cudaFuncAttributeMaxDynamicSharedMemorySize, SMEM_BYTES);

    zero_kernel<<<1, 128>>>();

    {
        int n4 = DOUT * DIN / 4;
        split2_kernel<<<n4 / 256, 256>>>((const float4*)Wm, (uint2*)W0, (uint2*)W1, n4);
    }
    {
        int n4 = (int)((size_t)MROWS * DIN / 4);
        split2_kernel<<<n4 / 256, 256>>>((const float4*)x, (uint2*)A0, (uint2*)A1, n4);
    }

    dim3 grid(DOUT / BN, MROWS / BM);            // (4, 512)
    gemm_bf16x4_kernel<<<grid, 256, SMEM_BYTES>>>(A0, A1, W0, W1, bias, currents);

    const int n_lanes = BATCH * DOUT;
    lif_flag_scan_kernel<<<n_lanes / 256, 256>>>(currents, out);

    dim3 fgrid(TSTEPS / 128, BATCH);             // (4, 128)
    fix_currents_kernel<<<fgrid, 256>>>(x, Wm, bias, currents);

    fix_scan_kernel<<<BATCH, 256>>>(currents, out);

    write_sum_kernel<<<1, 1>>>(out, out_size - 1);
}

// round 8
// speedup vs baseline: 1.0018x; 1.0018x over previous
#include <cuda_runtime.h>
#include <cuda_bf16.h>
#include <stdint.h>

// Problem constants
#define BATCH   128
#define TSTEPS  512
#define DIN     512
#define DOUT    512
#define MROWS   (BATCH * TSTEPS)        // 65536
#define BETA    0.95f
#define THRESH  1.0f
#define FLAG_EPS 2e-3f

// GEMM tiling
#define BM 128
#define BN 128
#define KC 32
#define NCHUNK (DIN / KC)               // 16
#define SRW 20                          // smem row stride in words (16 data + 4 pad)
#define SUBW (128 * SRW)                // 2560 words per sub-tile
#define STAGEW (4 * SUBW)               // A0 A1 B0 B1
#define SMEM_BYTES (2 * STAGEW * 4)     // 81920

// Persistent scratch (static device globals)
__device__ float g_currents[(size_t)MROWS * DOUT];                 // 128 MB
__device__ __nv_bfloat16 g_A0[(size_t)MROWS * DIN];                // 64 MB
__device__ __nv_bfloat16 g_A1[(size_t)MROWS * DIN];                // 64 MB
__device__ __nv_bfloat16 g_W0[(size_t)DOUT * DIN];
__device__ __nv_bfloat16 g_W1[(size_t)DOUT * DIN];
__device__ unsigned long long g_spike_count;
__device__ int g_bcount[BATCH];                  // flagged-lane count per batch
__device__ int g_bflag_d[BATCH * DOUT];          // flagged d list per batch

// ---------------------------------------------------------------------------
__global__ void zero_kernel() {
    if (threadIdx.x == 0) g_spike_count = 0ull;
    if (threadIdx.x < BATCH) g_bcount[threadIdx.x] = 0;
}

// ---------------------------------------------------------------------------
// 2-way bf16 split: x = b0 + b1 + O(2^-18 x)
// ---------------------------------------------------------------------------
__global__ __launch_bounds__(256)
void split2_kernel(const float4* __restrict__ src,
                   uint2* __restrict__ o0, uint2* __restrict__ o1, int n4)
{
    int i = blockIdx.x * blockDim.x + threadIdx.x;
    if (i >= n4) return;
    float4 v = src[i];
    float f[4] = {v.x, v.y, v.z, v.w};
    uint16_t h0[4], h1[4];
#pragma unroll
    for (int j = 0; j < 4; j++) {
        __nv_bfloat16 b0 = __float2bfloat16(f[j]);
        __nv_bfloat16 b1 = __float2bfloat16(f[j] - __bfloat162float(b0));
        h0[j] = __bfloat16_as_ushort(b0);
        h1[j] = __bfloat16_as_ushort(b1);
    }
    uint2 p0, p1;
    p0.x = ((uint32_t)h0[1] << 16) | h0[0];
    p0.y = ((uint32_t)h0[3] << 16) | h0[2];
    p1.x = ((uint32_t)h1[1] << 16) | h1[0];
    p1.y = ((uint32_t)h1[3] << 16) | h1[2];
    o0[i] = p0;
    o1[i] = p1;
}

// ---------------------------------------------------------------------------
// cp.async + mma helpers (sm_80 baseline PTX)
// ---------------------------------------------------------------------------
__device__ __forceinline__ uint32_t smem_u32(const void* p) {
    uint32_t a;
    asm("{ .reg .u64 t; cvta.to.shared.u64 t, %1; cvt.u32.u64 %0, t; }" : "=r"(a) : "l"(p));
    return a;
}
#define CP_ASYNC16(dst_u32, src_ptr) \
    asm volatile("cp.async.cg.shared.global [%0], [%1], 16;" :: "r"(dst_u32), "l"(src_ptr) : "memory")
#define CP_COMMIT() asm volatile("cp.async.commit_group;" ::: "memory")
#define CP_WAIT1()  asm volatile("cp.async.wait_group 1;" ::: "memory")
#define CP_WAIT0()  asm volatile("cp.async.wait_group 0;" ::: "memory")

__device__ __forceinline__ void mma_bf16(float* d, const uint32_t* a, const uint32_t* b) {
    asm volatile(
        "mma.sync.aligned.m16n8k16.row.col.f32.bf16.bf16.f32 "
        "{%0,%1,%2,%3}, {%4,%5,%6,%7}, {%8,%9}, {%0,%1,%2,%3};"
        : "+f"(d[0]), "+f"(d[1]), "+f"(d[2]), "+f"(d[3])
        : "r"(a[0]), "r"(a[1]), "r"(a[2]), "r"(a[3]), "r"(b[0]), "r"(b[1]));
}

// ---------------------------------------------------------------------------
// bf16x4 approx GEMM: C[m,n] = sum_k A[m,k]*W[n,k] + bias[n]  (err ~1e-6)
// ---------------------------------------------------------------------------
__global__ __launch_bounds__(256, 1)
void gemm_bf16x4_kernel(const __nv_bfloat16* __restrict__ A0,
                        const __nv_bfloat16* __restrict__ A1,
                        const __nv_bfloat16* __restrict__ B0,
                        const __nv_bfloat16* __restrict__ B1,
                        const float* __restrict__ bias,
                        float* __restrict__ C)
{
    extern __shared__ uint32_t smw[];
    const int tid  = threadIdx.x;
    const int wid  = tid >> 5;
    const int lane = tid & 31;
    const int wm = wid & 1;
    const int wn = wid >> 1;
    const int rowBase = blockIdx.y * BM;
    const int colBase = blockIdx.x * BN;
    const int q  = lane >> 2;
    const int tg = lane & 3;

    const uint32_t sb = smem_u32(smw);
    const __nv_bfloat16* Asrc[2] = {A0, A1};
    const __nv_bfloat16* Bsrc[2] = {B0, B1};

    float acc[4][4][4];
#pragma unroll
    for (int an = 0; an < 4; an++) {
        int c0 = colBase + wn * 32 + an * 8 + tg * 2;
        float b0 = __ldg(bias + c0), b1 = __ldg(bias + c0 + 1);
#pragma unroll
        for (int am = 0; am < 4; am++) {
            acc[am][an][0] = b0; acc[am][an][1] = b1;
            acc[am][an][2] = b0; acc[am][an][3] = b1;
        }
    }

    auto issue_chunk = [&](int j) {
        const uint32_t st = sb + (uint32_t)((j & 1) * STAGEW) * 4u;
        const int k0 = j * KC;
#pragma unroll
        for (int l = 0; l < 8; l++) {
            int idx = tid + l * 256;       // 0..2047
            int sub = idx >> 9;            // 0..3
            int t = idx & 511;
            int r = t >> 2;
            int c16 = t & 3;
            uint32_t doff = (uint32_t)(sub * SUBW + r * SRW + c16 * 4) * 4u;
            const __nv_bfloat16* src = (sub < 2)
                ? Asrc[sub] + (size_t)(rowBase + r) * DIN + k0 + c16 * 8
                : Bsrc[sub - 2] + (size_t)(colBase + r) * DIN + k0 + c16 * 8;
            CP_ASYNC16(st + doff, src);
        }
        CP_COMMIT();
    };

    issue_chunk(0);

    const int aRow = wm * 64 + q;
    const int bRow = wn * 32 + q;

    for (int j = 0; j < NCHUNK; j++) {
        if (j + 1 < NCHUNK) { issue_chunk(j + 1); CP_WAIT1(); }
        else                { CP_WAIT0(); }
        __syncthreads();

        const uint32_t* st = smw + (j & 1) * STAGEW;
        const uint32_t* sA = st;
        const uint32_t* sB = st + 2 * SUBW;

#pragma unroll
        for (int s = 0; s < 2; s++) {
            const int kb = s * 8 + tg;
            uint32_t af[2][4][4];
#pragma unroll
            for (int am = 0; am < 4; am++) {
                int r0 = (aRow + am * 16) * SRW + kb;
                int r1 = r0 + 8 * SRW;
#pragma unroll
                for (int p = 0; p < 2; p++) {
                    const uint32_t* a = sA + p * SUBW;
                    af[p][am][0] = a[r0];
                    af[p][am][1] = a[r1];
                    af[p][am][2] = a[r0 + 4];
                    af[p][am][3] = a[r1 + 4];
                }
            }
            uint32_t bf[2][4][2];
#pragma unroll
            for (int an = 0; an < 4; an++) {
                int rb = (bRow + an * 8) * SRW + kb;
#pragma unroll
                for (int p = 0; p < 2; p++) {
                    const uint32_t* b = sB + p * SUBW;
                    bf[p][an][0] = b[rb];
                    bf[p][an][1] = b[rb + 4];
                }
            }
#pragma unroll
            for (int am = 0; am < 4; am++)
#pragma unroll
                for (int an = 0; an < 4; an++) {
                    float* d = acc[am][an];
                    mma_bf16(d, af[1][am], bf[1][an]);
                    mma_bf16(d, af[1][am], bf[0][an]);
                    mma_bf16(d, af[0][am], bf[1][an]);
                    mma_bf16(d, af[0][am], bf[0][an]);
                }
        }
        __syncthreads();
    }

#pragma unroll
    for (int am = 0; am < 4; am++) {
        int r0 = rowBase + wm * 64 + am * 16 + q;
#pragma unroll
        for (int an = 0; an < 4; an++) {
            int c = colBase + wn * 32 + an * 8 + tg * 2;
            *(float2*)(C + (size_t)r0 * DOUT + c)       = make_float2(acc[am][an][0], acc[am][an][1]);
            *(float2*)(C + (size_t)(r0 + 8) * DOUT + c) = make_float2(acc[am][an][2], acc[am][an][3]);
        }
    }
}

// ---------------------------------------------------------------------------
// LIF flag scan: approx scan; flag lanes with any |mem-1| < FLAG_EPS.
// Counts spikes only for unflagged lanes; flagged lanes queued for fixup.
// ---------------------------------------------------------------------------
__global__ __launch_bounds__(256)
void lif_flag_scan_kernel(const float* __restrict__ cur,
                          float* __restrict__ spikes)
{
    const int idx = blockIdx.x * blockDim.x + threadIdx.x;
    const int b = idx >> 9;
    const int d = idx & (DOUT - 1);

    const float* cp = cur    + (size_t)b * TSTEPS * DOUT + d;
    float*       sp = spikes + (size_t)b * TSTEPS * DOUT + d;

    float mem = 0.0f;
    int cnt = 0;
    int flagged = 0;
#pragma unroll 8
    for (int t = 0; t < TSTEPS; t++) {
        float c = cp[(size_t)t * DOUT];
        mem = fmaf(BETA, mem, c);
        flagged |= (fabsf(mem - THRESH) < FLAG_EPS) ? 1 : 0;
        float spk = (mem > THRESH) ? 1.0f : 0.0f;
        mem -= spk * THRESH;
        sp[(size_t)t * DOUT] = spk;
        cnt += (spk > 0.0f) ? 1 : 0;
    }

    if (flagged) {
        cnt = 0;                                  // counted later, exactly
        int slot = atomicAdd(&g_bcount[b], 1);
        g_bflag_d[b * DOUT + slot] = d;
    }

#pragma unroll
    for (int off = 16; off > 0; off >>= 1)
        cnt += __shfl_down_sync(0xffffffffu, cnt, off);
    if ((threadIdx.x & 31) == 0 && cnt > 0)
        atomicAdd(&g_spike_count, (unsigned long long)cnt);
}

// ---------------------------------------------------------------------------
// Fixup phase A: exact fp32-chain currents for flagged lanes.
// Block = (t-tile, b). 256 threads = 32 t-slots x 8 d-slots, thread tile 4t x 4d.
// k ascending fmaf chain + bias at end — bit-identical to the round-1 kernel.
// ---------------------------------------------------------------------------
#define XS_STRIDE 36
__global__ __launch_bounds__(256)
void fix_currents_kernel(const float* __restrict__ x,
                         const float* __restrict__ Wm,
                         const float* __restrict__ bias,
                         float* __restrict__ C)
{
    const int b  = blockIdx.y;
    const int t0 = blockIdx.x * 128;
    const int nd = g_bcount[b];
    if (nd == 0) return;

    __shared__ float xs[128 * XS_STRIDE];    // 18 KB
    __shared__ float ws[32 * XS_STRIDE];     // 4.5 KB
    __shared__ int   dlist[32];

    const int tid = threadIdx.x;
    const int ts = tid >> 3;       // 0..31 -> t rows ts*4 + i
    const int ds = tid & 7;        // 0..7  -> d cols ds*4 + jj

    for (int dc = 0; dc < nd; dc += 32) {
        __syncthreads();
        if (tid < 32) {
            int j = dc + tid;
            dlist[tid] = g_bflag_d[b * DOUT + ((j < nd) ? j : (nd - 1))];
        }

        float acc[4][4];
#pragma unroll
        for (int i = 0; i < 4; i++)
#pragma unroll
            for (int jj = 0; jj < 4; jj++) acc[i][jj] = 0.0f;

        for (int k0 = 0; k0 < DIN; k0 += 32) {
            __syncthreads();
            // stage x tile: 128 t-rows x 32 k (float4 loads, 4/thread)
#pragma unroll
            for (int l = 0; l < 4; l++) {
                int idx = tid + l * 256;          // 0..1023
                int r = idx >> 3, c4 = idx & 7;
                float4 v = *(const float4*)(x + ((size_t)b * TSTEPS + t0 + r) * DIN + k0 + c4 * 4);
                *(float4*)(xs + r * XS_STRIDE + c4 * 4) = v;
            }
            // stage W rows for the 32 flagged d's (1 float4/thread)
            {
                int r = tid >> 3, c4 = tid & 7;   // 32 rows x 8
                float4 v = *(const float4*)(Wm + (size_t)dlist[r] * DIN + k0 + c4 * 4);
                *(float4*)(ws + r * XS_STRIDE + c4 * 4) = v;
            }
            __syncthreads();

            // exact chain: k ascending
            for (int k = 0; k < 32; k++) {
                float wv[4], xv[4];
#pragma unroll
                for (int jj = 0; jj < 4; jj++) wv[jj] = ws[(ds * 4 + jj) * XS_STRIDE + k];
#pragma unroll
                for (int i = 0; i < 4; i++) xv[i] = xs[(ts * 4 + i) * XS_STRIDE + k];
#pragma unroll
                for (int i = 0; i < 4; i++)
#pragma unroll
                    for (int jj = 0; jj < 4; jj++)
                        acc[i][jj] = fmaf(xv[i], wv[jj], acc[i][jj]);
            }
        }

        // write exact currents (+bias, at end — matches reference order)
#pragma unroll
        for (int jj = 0; jj < 4; jj++) {
            int j = dc + ds * 4 + jj;
            if (j < nd) {
                int d = dlist[ds * 4 + jj];
                float bv = bias[d];
#pragma unroll
                for (int i = 0; i < 4; i++) {
                    int t = t0 + ts * 4 + i;
                    C[((size_t)b * TSTEPS + t) * DOUT + d] = acc[i][jj] + bv;
                }
            }
        }
    }
}

// ---------------------------------------------------------------------------
// Fixup phase B: exact rescan of flagged lanes; overwrite spikes, add counts.
// ---------------------------------------------------------------------------
__global__ __launch_bounds__(256)
void fix_scan_kernel(const float* __restrict__ cur,
                     float* __restrict__ spikes)
{
    const int b = blockIdx.x;
    const int nd = g_bcount[b];

    for (int slot = threadIdx.x; slot < nd; slot += blockDim.x) {
        const int d = g_bflag_d[b * DOUT + slot];
        const float* cp = cur    + (size_t)b * TSTEPS * DOUT + d;
        float*       sp = spikes + (size_t)b * TSTEPS * DOUT + d;

        float mem = 0.0f;
        int cnt = 0;
        for (int t = 0; t < TSTEPS; t++) {
            float c = cp[(size_t)t * DOUT];
            mem = fmaf(BETA, mem, c);
            float spk = (mem > THRESH) ? 1.0f : 0.0f;
            mem -= spk * THRESH;
            sp[(size_t)t * DOUT] = spk;
            cnt += (spk > 0.0f) ? 1 : 0;
        }
        atomicAdd(&g_spike_count, (unsigned long long)cnt);
    }
}

__global__ void write_sum_kernel(float* __restrict__ out, int sum_idx) {
    out[sum_idx] = (float)g_spike_count;
}

// ---------------------------------------------------------------------------
extern "C" void kernel_launch(void* const* d_in, const int* in_sizes, int n_in,
                              void* d_out, int out_size)
{
    const float* x    = (const float*)d_in[0];   // [B, T, DIN]
    const float* Wm   = (const float*)d_in[1];   // [DOUT, DIN]
    const float* bias = (const float*)d_in[2];   // [DOUT]
    float* out = (float*)d_out;

    float* currents;
    __nv_bfloat16 *A0, *A1, *W0, *W1;
    cudaGetSymbolAddress((void**)&currents, g_currents);
    cudaGetSymbolAddress((void**)&A0, g_A0);
    cudaGetSymbolAddress((void**)&A1, g_A1);
    cudaGetSymbolAddress((void**)&W0, g_W0);
    cudaGetSymbolAddress((void**)&W1, g_W1);

    cudaFuncSetAttribute(gemm_bf16x4_kernel,
                         cudaFuncAttributeMaxDynamicSharedMemorySize, SMEM_BYTES);

    zero_kernel<<<1, 128>>>();

    {
        int n4 = DOUT * DIN / 4;
        split2_kernel<<<n4 / 256, 256>>>((const float4*)Wm, (uint2*)W0, (uint2*)W1, n4);
    }
    {
        int n4 = (int)((size_t)MROWS * DIN / 4);
        split2_kernel<<<n4 / 256, 256>>>((const float4*)x, (uint2*)A0, (uint2*)A1, n4);
    }

    dim3 grid(DOUT / BN, MROWS / BM);            // (4, 512)
    gemm_bf16x4_kernel<<<grid, 256, SMEM_BYTES>>>(A0, A1, W0, W1, bias, currents);

    const int n_lanes = BATCH * DOUT;
    lif_flag_scan_kernel<<<n_lanes / 256, 256>>>(currents, out);

    dim3 fgrid(TSTEPS / 128, BATCH);             // (4, 128)
    fix_currents_kernel<<<fgrid, 256>>>(x, Wm, bias, currents);

    fix_scan_kernel<<<BATCH, 256>>>(currents, out);

    write_sum_kernel<<<1, 1>>>(out, out_size - 1);
}

// round 9
// speedup vs baseline: 1.0137x; 1.0119x over previous
#include <cuda_runtime.h>
#include <cuda_bf16.h>
#include <stdint.h>

// Problem constants
#define BATCH   128
#define TSTEPS  512
#define DIN     512
#define DOUT    512
#define MROWS   (BATCH * TSTEPS)        // 65536
#define BETA    0.95f
#define THRESH  1.0f
#define FLAG_EPS 2e-3f

// GEMM tiling
#define BM 128
#define BN 128
#define KC 32
#define NCHUNK (DIN / KC)               // 16
#define SRW 20                          // smem row stride in words (16 data + 4 pad)
#define SUBW (128 * SRW)                // 2560 words per sub-tile
#define STAGEW (4 * SUBW)               // Ahi Alo Whi Wlo
#define SMEM_BYTES (2 * STAGEW * 4)     // 81920

// Persistent scratch (static device globals)
__device__ float g_currents[(size_t)MROWS * DOUT];                 // 128 MB
__device__ __nv_bfloat16 g_W0[(size_t)DOUT * DIN];
__device__ __nv_bfloat16 g_W1[(size_t)DOUT * DIN];
__device__ unsigned long long g_spike_count;
__device__ int g_bcount[BATCH];                  // flagged-lane count per batch
__device__ int g_bflag_d[BATCH * DOUT];          // flagged d list per batch

// ---------------------------------------------------------------------------
__global__ void zero_kernel() {
    if (threadIdx.x == 0) g_spike_count = 0ull;
    if (threadIdx.x < BATCH) g_bcount[threadIdx.x] = 0;
}

// ---------------------------------------------------------------------------
// 2-way bf16 split for W only (1 MB — negligible)
// ---------------------------------------------------------------------------
__global__ __launch_bounds__(256)
void split2_kernel(const float4* __restrict__ src,
                   uint2* __restrict__ o0, uint2* __restrict__ o1, int n4)
{
    int i = blockIdx.x * blockDim.x + threadIdx.x;
    if (i >= n4) return;
    float4 v = src[i];
    float f[4] = {v.x, v.y, v.z, v.w};
    uint16_t h0[4], h1[4];
#pragma unroll
    for (int j = 0; j < 4; j++) {
        __nv_bfloat16 b0 = __float2bfloat16(f[j]);
        __nv_bfloat16 b1 = __float2bfloat16(f[j] - __bfloat162float(b0));
        h0[j] = __bfloat16_as_ushort(b0);
        h1[j] = __bfloat16_as_ushort(b1);
    }
    uint2 p0, p1;
    p0.x = ((uint32_t)h0[1] << 16) | h0[0];
    p0.y = ((uint32_t)h0[3] << 16) | h0[2];
    p1.x = ((uint32_t)h1[1] << 16) | h1[0];
    p1.y = ((uint32_t)h1[3] << 16) | h1[2];
    o0[i] = p0;
    o1[i] = p1;
}

// ---------------------------------------------------------------------------
// cp.async + mma helpers (sm_80 baseline PTX)
// ---------------------------------------------------------------------------
__device__ __forceinline__ uint32_t smem_u32(const void* p) {
    uint32_t a;
    asm("{ .reg .u64 t; cvta.to.shared.u64 t, %1; cvt.u32.u64 %0, t; }" : "=r"(a) : "l"(p));
    return a;
}
#define CP_ASYNC16(dst_u32, src_ptr) \
    asm volatile("cp.async.cg.shared.global [%0], [%1], 16;" :: "r"(dst_u32), "l"(src_ptr) : "memory")
#define CP_COMMIT() asm volatile("cp.async.commit_group;" ::: "memory")
#define CP_WAIT0()  asm volatile("cp.async.wait_group 0;" ::: "memory")

__device__ __forceinline__ void mma_bf16(float* d, const uint32_t* a, const uint32_t* b) {
    asm volatile(
        "mma.sync.aligned.m16n8k16.row.col.f32.bf16.bf16.f32 "
        "{%0,%1,%2,%3}, {%4,%5,%6,%7}, {%8,%9}, {%0,%1,%2,%3};"
        : "+f"(d[0]), "+f"(d[1]), "+f"(d[2]), "+f"(d[3])
        : "r"(a[0]), "r"(a[1]), "r"(a[2]), "r"(a[3]), "r"(b[0]), "r"(b[1]));
}

// convert one float4 to packed bf16 hi/lo pairs (identical math to split2_kernel)
__device__ __forceinline__ void cvt_hi_lo(float4 v, uint2& hi, uint2& lo) {
    float f[4] = {v.x, v.y, v.z, v.w};
    uint16_t h0[4], h1[4];
#pragma unroll
    for (int j = 0; j < 4; j++) {
        __nv_bfloat16 b0 = __float2bfloat16(f[j]);
        __nv_bfloat16 b1 = __float2bfloat16(f[j] - __bfloat162float(b0));
        h0[j] = __bfloat16_as_ushort(b0);
        h1[j] = __bfloat16_as_ushort(b1);
    }
    hi.x = ((uint32_t)h0[1] << 16) | h0[0];
    hi.y = ((uint32_t)h0[3] << 16) | h0[2];
    lo.x = ((uint32_t)h1[1] << 16) | h1[0];
    lo.y = ((uint32_t)h1[3] << 16) | h1[2];
}

// ---------------------------------------------------------------------------
// bf16x4 approx GEMM with fused A split:
//   C[m,n] = sum_k A[m,k]*W[n,k] + bias[n]   (err ~1e-6 rms, ~1e-5 max)
// A read as fp32 and split in-register; W pre-split, fetched via cp.async.
// ---------------------------------------------------------------------------
__global__ __launch_bounds__(256, 1)
void gemm_bf16x4_kernel(const float* __restrict__ A,
                        const __nv_bfloat16* __restrict__ B0,
                        const __nv_bfloat16* __restrict__ B1,
                        const float* __restrict__ bias,
                        float* __restrict__ C)
{
    extern __shared__ uint32_t smw[];
    const int tid  = threadIdx.x;
    const int wid  = tid >> 5;
    const int lane = tid & 31;
    const int wm = wid & 1;
    const int wn = wid >> 1;
    const int rowBase = blockIdx.y * BM;
    const int colBase = blockIdx.x * BN;
    const int q  = lane >> 2;
    const int tg = lane & 3;

    const uint32_t sb = smem_u32(smw);

    // A producer mapping: 1024 float4 slots (128 rows x 8), 4 per thread
    int ar[4], ac4[4];
#pragma unroll
    for (int l = 0; l < 4; l++) {
        int idx = tid + l * 256;
        ar[l]  = idx >> 3;
        ac4[l] = idx & 7;
    }

    float acc[4][4][4];
#pragma unroll
    for (int an = 0; an < 4; an++) {
        int c0 = colBase + wn * 32 + an * 8 + tg * 2;
        float b0 = __ldg(bias + c0), b1 = __ldg(bias + c0 + 1);
#pragma unroll
        for (int am = 0; am < 4; am++) {
            acc[am][an][0] = b0; acc[am][an][1] = b1;
            acc[am][an][2] = b0; acc[am][an][3] = b1;
        }
    }

    auto ldg_a = [&](int j, float4* ra) {
        const int k0 = j * KC;
#pragma unroll
        for (int l = 0; l < 4; l++)
            ra[l] = *(const float4*)(A + (size_t)(rowBase + ar[l]) * DIN + k0 + ac4[l] * 4);
    };
    auto sts_a = [&](int stage, const float4* ra) {
        uint32_t* st = smw + stage * STAGEW;
#pragma unroll
        for (int l = 0; l < 4; l++) {
            uint2 hi, lo;
            cvt_hi_lo(ra[l], hi, lo);
            int off = ar[l] * SRW + ac4[l] * 2;
            *(uint2*)(st + off)        = hi;
            *(uint2*)(st + SUBW + off) = lo;
        }
    };
    auto cpasync_w = [&](int j) {
        const uint32_t st = sb + (uint32_t)((j & 1) * STAGEW + 2 * SUBW) * 4u;
        const int k0 = j * KC;
#pragma unroll
        for (int l = 0; l < 4; l++) {
            int idx = tid + l * 256;       // 0..1023
            int sub = idx >> 9;            // 0..1 (hi / lo)
            int t = idx & 511;
            int r = t >> 2;
            int c16 = t & 3;
            uint32_t doff = (uint32_t)(sub * SUBW + r * SRW + c16 * 4) * 4u;
            const __nv_bfloat16* src = ((sub == 0) ? B0 : B1)
                + (size_t)(colBase + r) * DIN + k0 + c16 * 8;
            CP_ASYNC16(st + doff, src);
        }
        CP_COMMIT();
    };

    // ---- prologue: stage chunk 0, prefetch A chunk 1 ----
    float4 ra[4];
    ldg_a(0, ra);
    cpasync_w(0);
    sts_a(0, ra);
    ldg_a(1, ra);
    CP_WAIT0();
    __syncthreads();

    const int aRow = wm * 64 + q;
    const int bRow = wn * 32 + q;

    for (int j = 0; j < NCHUNK; j++) {
        if (j + 1 < NCHUNK) cpasync_w(j + 1);

        // ---- compute chunk j ----
        const uint32_t* st = smw + (j & 1) * STAGEW;
        const uint32_t* sA = st;
        const uint32_t* sB = st + 2 * SUBW;

#pragma unroll
        for (int s = 0; s < 2; s++) {
            const int kb = s * 8 + tg;
            uint32_t af[2][4][4];
#pragma unroll
            for (int am = 0; am < 4; am++) {
                int r0 = (aRow + am * 16) * SRW + kb;
                int r1 = r0 + 8 * SRW;
#pragma unroll
                for (int p = 0; p < 2; p++) {
                    const uint32_t* a = sA + p * SUBW;
                    af[p][am][0] = a[r0];
                    af[p][am][1] = a[r1];
                    af[p][am][2] = a[r0 + 4];
                    af[p][am][3] = a[r1 + 4];
                }
            }
            uint32_t bf[2][4][2];
#pragma unroll
            for (int an = 0; an < 4; an++) {
                int rb = (bRow + an * 8) * SRW + kb;
#pragma unroll
                for (int p = 0; p < 2; p++) {
                    const uint32_t* b = sB + p * SUBW;
                    bf[p][an][0] = b[rb];
                    bf[p][an][1] = b[rb + 4];
                }
            }
#pragma unroll
            for (int am = 0; am < 4; am++)
#pragma unroll
                for (int an = 0; an < 4; an++) {
                    float* d = acc[am][an];
                    mma_bf16(d, af[1][am], bf[1][an]);
                    mma_bf16(d, af[1][am], bf[0][an]);
                    mma_bf16(d, af[0][am], bf[1][an]);
                    mma_bf16(d, af[0][am], bf[0][an]);
                }
        }

        // ---- stage chunk j+1 (A from regs), prefetch A chunk j+2 ----
        if (j + 1 < NCHUNK) {
            sts_a((j + 1) & 1, ra);
            if (j + 2 < NCHUNK) ldg_a(j + 2, ra);
            CP_WAIT0();
        }
        __syncthreads();
    }

#pragma unroll
    for (int am = 0; am < 4; am++) {
        int r0 = rowBase + wm * 64 + am * 16 + q;
#pragma unroll
        for (int an = 0; an < 4; an++) {
            int c = colBase + wn * 32 + an * 8 + tg * 2;
            *(float2*)(C + (size_t)r0 * DOUT + c)       = make_float2(acc[am][an][0], acc[am][an][1]);
            *(float2*)(C + (size_t)(r0 + 8) * DOUT + c) = make_float2(acc[am][an][2], acc[am][an][3]);
        }
    }
}

// ---------------------------------------------------------------------------
// LIF flag scan: approx scan; flag lanes with any |mem-1| < FLAG_EPS.
// ---------------------------------------------------------------------------
__global__ __launch_bounds__(256)
void lif_flag_scan_kernel(const float* __restrict__ cur,
                          float* __restrict__ spikes)
{
    const int idx = blockIdx.x * blockDim.x + threadIdx.x;
    const int b = idx >> 9;
    const int d = idx & (DOUT - 1);

    const float* cp = cur    + (size_t)b * TSTEPS * DOUT + d;
    float*       sp = spikes + (size_t)b * TSTEPS * DOUT + d;

    float mem = 0.0f;
    int cnt = 0;
    int flagged = 0;
#pragma unroll 8
    for (int t = 0; t < TSTEPS; t++) {
        float c = cp[(size_t)t * DOUT];
        mem = fmaf(BETA, mem, c);
        flagged |= (fabsf(mem - THRESH) < FLAG_EPS) ? 1 : 0;
        float spk = (mem > THRESH) ? 1.0f : 0.0f;
        mem -= spk * THRESH;
        sp[(size_t)t * DOUT] = spk;
        cnt += (spk > 0.0f) ? 1 : 0;
    }

    if (flagged) {
        cnt = 0;
        int slot = atomicAdd(&g_bcount[b], 1);
        g_bflag_d[b * DOUT + slot] = d;
    }

#pragma unroll
    for (int off = 16; off > 0; off >>= 1)
        cnt += __shfl_down_sync(0xffffffffu, cnt, off);
    if ((threadIdx.x & 31) == 0 && cnt > 0)
        atomicAdd(&g_spike_count, (unsigned long long)cnt);
}

// ---------------------------------------------------------------------------
// Fixup phase A: exact fp32-chain currents for flagged lanes (round-1 order).
// ---------------------------------------------------------------------------
#define XS_STRIDE 36
__global__ __launch_bounds__(256)
void fix_currents_kernel(const float* __restrict__ x,
                         const float* __restrict__ Wm,
                         const float* __restrict__ bias,
                         float* __restrict__ C)
{
    const int b  = blockIdx.y;
    const int t0 = blockIdx.x * 128;
    const int nd = g_bcount[b];
    if (nd == 0) return;

    __shared__ float xs[128 * XS_STRIDE];
    __shared__ float ws[32 * XS_STRIDE];
    __shared__ int   dlist[32];

    const int tid = threadIdx.x;
    const int ts = tid >> 3;
    const int ds = tid & 7;

    for (int dc = 0; dc < nd; dc += 32) {
        __syncthreads();
        if (tid < 32) {
            int j = dc + tid;
            dlist[tid] = g_bflag_d[b * DOUT + ((j < nd) ? j : (nd - 1))];
        }

        float acc[4][4];
#pragma unroll
        for (int i = 0; i < 4; i++)
#pragma unroll
            for (int jj = 0; jj < 4; jj++) acc[i][jj] = 0.0f;

        for (int k0 = 0; k0 < DIN; k0 += 32) {
            __syncthreads();
#pragma unroll
            for (int l = 0; l < 4; l++) {
                int idx = tid + l * 256;
                int r = idx >> 3, c4 = idx & 7;
                float4 v = *(const float4*)(x + ((size_t)b * TSTEPS + t0 + r) * DIN + k0 + c4 * 4);
                *(float4*)(xs + r * XS_STRIDE + c4 * 4) = v;
            }
            {
                int r = tid >> 3, c4 = tid & 7;
                float4 v = *(const float4*)(Wm + (size_t)dlist[r] * DIN + k0 + c4 * 4);
                *(float4*)(ws + r * XS_STRIDE + c4 * 4) = v;
            }
            __syncthreads();

            for (int k = 0; k < 32; k++) {
                float wv[4], xv[4];
#pragma unroll
                for (int jj = 0; jj < 4; jj++) wv[jj] = ws[(ds * 4 + jj) * XS_STRIDE + k];
#pragma unroll
                for (int i = 0; i < 4; i++) xv[i] = xs[(ts * 4 + i) * XS_STRIDE + k];
#pragma unroll
                for (int i = 0; i < 4; i++)
#pragma unroll
                    for (int jj = 0; jj < 4; jj++)
                        acc[i][jj] = fmaf(xv[i], wv[jj], acc[i][jj]);
            }
        }

#pragma unroll
        for (int jj = 0; jj < 4; jj++) {
            int j = dc + ds * 4 + jj;
            if (j < nd) {
                int d = dlist[ds * 4 + jj];
                float bv = bias[d];
#pragma unroll
                for (int i = 0; i < 4; i++) {
                    int t = t0 + ts * 4 + i;
                    C[((size_t)b * TSTEPS + t) * DOUT + d] = acc[i][jj] + bv;
                }
            }
        }
    }
}

// ---------------------------------------------------------------------------
// Fixup phase B: exact rescan of flagged lanes. Parallel strata + MLP unroll.
// ---------------------------------------------------------------------------
__global__ __launch_bounds__(32)
void fix_scan_kernel(const float* __restrict__ cur,
                     float* __restrict__ spikes)
{
    const int b = blockIdx.x;
    const int nd = g_bcount[b];

    for (int slot = blockIdx.y * 32 + threadIdx.x; slot < nd; slot += 8 * 32) {
        const int d = g_bflag_d[b * DOUT + slot];
        const float* cp = cur    + (size_t)b * TSTEPS * DOUT + d;
        float*       sp = spikes + (size_t)b * TSTEPS * DOUT + d;

        float mem = 0.0f;
        int cnt = 0;
#pragma unroll 8
        for (int t = 0; t < TSTEPS; t++) {
            float c = cp[(size_t)t * DOUT];
            mem = fmaf(BETA, mem, c);
            float spk = (mem > THRESH) ? 1.0f : 0.0f;
            mem -= spk * THRESH;
            sp[(size_t)t * DOUT] = spk;
            cnt += (spk > 0.0f) ? 1 : 0;
        }
        atomicAdd(&g_spike_count, (unsigned long long)cnt);
    }
}

__global__ void write_sum_kernel(float* __restrict__ out, int sum_idx) {
    out[sum_idx] = (float)g_spike_count;
}

// ---------------------------------------------------------------------------
extern "C" void kernel_launch(void* const* d_in, const int* in_sizes, int n_in,
                              void* d_out, int out_size)
{
    const float* x    = (const float*)d_in[0];   // [B, T, DIN]
    const float* Wm   = (const float*)d_in[1];   // [DOUT, DIN]
    const float* bias = (const float*)d_in[2];   // [DOUT]
    float* out = (float*)d_out;

    float* currents;
    __nv_bfloat16 *W0, *W1;
    cudaGetSymbolAddress((void**)&currents, g_currents);
    cudaGetSymbolAddress((void**)&W0, g_W0);
    cudaGetSymbolAddress((void**)&W1, g_W1);

    cudaFuncSetAttribute(gemm_bf16x4_kernel,
                         cudaFuncAttributeMaxDynamicSharedMemorySize, SMEM_BYTES);

    zero_kernel<<<1, 128>>>();

    {
        int n4 = DOUT * DIN / 4;
        split2_kernel<<<n4 / 256, 256>>>((const float4*)Wm, (uint2*)W0, (uint2*)W1, n4);
    }

    dim3 grid(DOUT / BN, MROWS / BM);            // (4, 512)
    gemm_bf16x4_kernel<<<grid, 256, SMEM_BYTES>>>(x, W0, W1, bias, currents);

    const int n_lanes = BATCH * DOUT;
    lif_flag_scan_kernel<<<n_lanes / 256, 256>>>(currents, out);

    dim3 fgrid(TSTEPS / 128, BATCH);             // (4, 128)
    fix_currents_kernel<<<fgrid, 256>>>(x, Wm, bias, currents);

    fix_scan_kernel<<<dim3(BATCH, 8), 32>>>(currents, out);

    write_sum_kernel<<<1, 1>>>(out, out_size - 1);
}

// round 10
// speedup vs baseline: 1.0138x; 1.0002x over previous
#include <cuda_runtime.h>
#include <cuda_bf16.h>
#include <stdint.h>

// Problem constants
#define BATCH   128
#define TSTEPS  512
#define DIN     512
#define DOUT    512
#define MROWS   (BATCH * TSTEPS)        // 65536
#define BETA    0.95f
#define THRESH  1.0f
#define FLAG_EPS 2e-3f

// GEMM tiling
#define BM 128
#define BN 128
#define KC 32
#define NCHUNK (DIN / KC)               // 16
#define SRW 20                          // smem row stride in words (16 data + 4 pad)
#define SUBW (128 * SRW)                // 2560 words per sub-tile
#define STAGEW (4 * SUBW)               // Ahi Alo Whi Wlo
#define SMEM_BYTES (2 * STAGEW * 4)     // 81920

// Persistent scratch (static device globals)
__device__ float g_currents[(size_t)MROWS * DOUT];                 // 128 MB
__device__ __nv_bfloat16 g_W0[(size_t)DOUT * DIN];
__device__ __nv_bfloat16 g_W1[(size_t)DOUT * DIN];
__device__ unsigned long long g_spike_count;
__device__ int g_bcount[BATCH];                  // flagged-lane count per batch
__device__ int g_bflag_d[BATCH * DOUT];          // flagged d list per batch

// ---------------------------------------------------------------------------
__global__ void zero_kernel() {
    if (threadIdx.x == 0) g_spike_count = 0ull;
    if (threadIdx.x < BATCH) g_bcount[threadIdx.x] = 0;
}

// ---------------------------------------------------------------------------
// 2-way bf16 split for W only (1 MB — negligible)
// ---------------------------------------------------------------------------
__global__ __launch_bounds__(256)
void split2_kernel(const float4* __restrict__ src,
                   uint2* __restrict__ o0, uint2* __restrict__ o1, int n4)
{
    int i = blockIdx.x * blockDim.x + threadIdx.x;
    if (i >= n4) return;
    float4 v = src[i];
    float f[4] = {v.x, v.y, v.z, v.w};
    uint16_t h0[4], h1[4];
#pragma unroll
    for (int j = 0; j < 4; j++) {
        __nv_bfloat16 b0 = __float2bfloat16(f[j]);
        __nv_bfloat16 b1 = __float2bfloat16(f[j] - __bfloat162float(b0));
        h0[j] = __bfloat16_as_ushort(b0);
        h1[j] = __bfloat16_as_ushort(b1);
    }
    uint2 p0, p1;
    p0.x = ((uint32_t)h0[1] << 16) | h0[0];
    p0.y = ((uint32_t)h0[3] << 16) | h0[2];
    p1.x = ((uint32_t)h1[1] << 16) | h1[0];
    p1.y = ((uint32_t)h1[3] << 16) | h1[2];
    o0[i] = p0;
    o1[i] = p1;
}

// ---------------------------------------------------------------------------
// cp.async + mma helpers (sm_80 baseline PTX)
// ---------------------------------------------------------------------------
__device__ __forceinline__ uint32_t smem_u32(const void* p) {
    uint32_t a;
    asm("{ .reg .u64 t; cvta.to.shared.u64 t, %1; cvt.u32.u64 %0, t; }" : "=r"(a) : "l"(p));
    return a;
}
#define CP_ASYNC16(dst_u32, src_ptr) \
    asm volatile("cp.async.cg.shared.global [%0], [%1], 16;" :: "r"(dst_u32), "l"(src_ptr) : "memory")
#define CP_COMMIT() asm volatile("cp.async.commit_group;" ::: "memory")
#define CP_WAIT0()  asm volatile("cp.async.wait_group 0;" ::: "memory")

__device__ __forceinline__ void mma_bf16(float* d, const uint32_t* a, const uint32_t* b) {
    asm volatile(
        "mma.sync.aligned.m16n8k16.row.col.f32.bf16.bf16.f32 "
        "{%0,%1,%2,%3}, {%4,%5,%6,%7}, {%8,%9}, {%0,%1,%2,%3};"
        : "+f"(d[0]), "+f"(d[1]), "+f"(d[2]), "+f"(d[3])
        : "r"(a[0]), "r"(a[1]), "r"(a[2]), "r"(a[3]), "r"(b[0]), "r"(b[1]));
}

// convert one float4 to packed bf16 hi/lo pairs (identical math to split2_kernel)
__device__ __forceinline__ void cvt_hi_lo(float4 v, uint2& hi, uint2& lo) {
    float f[4] = {v.x, v.y, v.z, v.w};
    uint16_t h0[4], h1[4];
#pragma unroll
    for (int j = 0; j < 4; j++) {
        __nv_bfloat16 b0 = __float2bfloat16(f[j]);
        __nv_bfloat16 b1 = __float2bfloat16(f[j] - __bfloat162float(b0));
        h0[j] = __bfloat16_as_ushort(b0);
        h1[j] = __bfloat16_as_ushort(b1);
    }
    hi.x = ((uint32_t)h0[1] << 16) | h0[0];
    hi.y = ((uint32_t)h0[3] << 16) | h0[2];
    lo.x = ((uint32_t)h1[1] << 16) | h1[0];
    lo.y = ((uint32_t)h1[3] << 16) | h1[2];
}

// ---------------------------------------------------------------------------
// bf16x4 approx GEMM with fused A split:
//   C[m,n] = sum_k A[m,k]*W[n,k] + bias[n]   (err ~1e-6 rms, ~1e-5 max)
// A read as fp32 and split in-register; W pre-split, fetched via cp.async.
// ---------------------------------------------------------------------------
__global__ __launch_bounds__(256, 1)
void gemm_bf16x4_kernel(const float* __restrict__ A,
                        const __nv_bfloat16* __restrict__ B0,
                        const __nv_bfloat16* __restrict__ B1,
                        const float* __restrict__ bias,
                        float* __restrict__ C)
{
    extern __shared__ uint32_t smw[];
    const int tid  = threadIdx.x;
    const int wid  = tid >> 5;
    const int lane = tid & 31;
    const int wm = wid & 1;
    const int wn = wid >> 1;
    const int rowBase = blockIdx.y * BM;
    const int colBase = blockIdx.x * BN;
    const int q  = lane >> 2;
    const int tg = lane & 3;

    const uint32_t sb = smem_u32(smw);

    // A producer mapping: 1024 float4 slots (128 rows x 8), 4 per thread
    int ar[4], ac4[4];
#pragma unroll
    for (int l = 0; l < 4; l++) {
        int idx = tid + l * 256;
        ar[l]  = idx >> 3;
        ac4[l] = idx & 7;
    }

    float acc[4][4][4];
#pragma unroll
    for (int an = 0; an < 4; an++) {
        int c0 = colBase + wn * 32 + an * 8 + tg * 2;
        float b0 = __ldg(bias + c0), b1 = __ldg(bias + c0 + 1);
#pragma unroll
        for (int am = 0; am < 4; am++) {
            acc[am][an][0] = b0; acc[am][an][1] = b1;
            acc[am][an][2] = b0; acc[am][an][3] = b1;
        }
    }

    auto ldg_a = [&](int j, float4* ra) {
        const int k0 = j * KC;
#pragma unroll
        for (int l = 0; l < 4; l++)
            ra[l] = *(const float4*)(A + (size_t)(rowBase + ar[l]) * DIN + k0 + ac4[l] * 4);
    };
    auto sts_a = [&](int stage, const float4* ra) {
        uint32_t* st = smw + stage * STAGEW;
#pragma unroll
        for (int l = 0; l < 4; l++) {
            uint2 hi, lo;
            cvt_hi_lo(ra[l], hi, lo);
            int off = ar[l] * SRW + ac4[l] * 2;
            *(uint2*)(st + off)        = hi;
            *(uint2*)(st + SUBW + off) = lo;
        }
    };
    auto cpasync_w = [&](int j) {
        const uint32_t st = sb + (uint32_t)((j & 1) * STAGEW + 2 * SUBW) * 4u;
        const int k0 = j * KC;
#pragma unroll
        for (int l = 0; l < 4; l++) {
            int idx = tid + l * 256;       // 0..1023
            int sub = idx >> 9;            // 0..1 (hi / lo)
            int t = idx & 511;
            int r = t >> 2;
            int c16 = t & 3;
            uint32_t doff = (uint32_t)(sub * SUBW + r * SRW + c16 * 4) * 4u;
            const __nv_bfloat16* src = ((sub == 0) ? B0 : B1)
                + (size_t)(colBase + r) * DIN + k0 + c16 * 8;
            CP_ASYNC16(st + doff, src);
        }
        CP_COMMIT();
    };

    // ---- prologue: stage chunk 0, prefetch A chunk 1 ----
    float4 ra[4];
    ldg_a(0, ra);
    cpasync_w(0);
    sts_a(0, ra);
    ldg_a(1, ra);
    CP_WAIT0();
    __syncthreads();

    const int aRow = wm * 64 + q;
    const int bRow = wn * 32 + q;

    for (int j = 0; j < NCHUNK; j++) {
        if (j + 1 < NCHUNK) cpasync_w(j + 1);

        // ---- compute chunk j ----
        const uint32_t* st = smw + (j & 1) * STAGEW;
        const uint32_t* sA = st;
        const uint32_t* sB = st + 2 * SUBW;

#pragma unroll
        for (int s = 0; s < 2; s++) {
            const int kb = s * 8 + tg;
            uint32_t af[2][4][4];
#pragma unroll
            for (int am = 0; am < 4; am++) {
                int r0 = (aRow + am * 16) * SRW + kb;
                int r1 = r0 + 8 * SRW;
#pragma unroll
                for (int p = 0; p < 2; p++) {
                    const uint32_t* a = sA + p * SUBW;
                    af[p][am][0] = a[r0];
                    af[p][am][1] = a[r1];
                    af[p][am][2] = a[r0 + 4];
                    af[p][am][3] = a[r1 + 4];
                }
            }
            uint32_t bf[2][4][2];
#pragma unroll
            for (int an = 0; an < 4; an++) {
                int rb = (bRow + an * 8) * SRW + kb;
#pragma unroll
                for (int p = 0; p < 2; p++) {
                    const uint32_t* b = sB + p * SUBW;
                    bf[p][an][0] = b[rb];
                    bf[p][an][1] = b[rb + 4];
                }
            }
#pragma unroll
            for (int am = 0; am < 4; am++)
#pragma unroll
                for (int an = 0; an < 4; an++) {
                    float* d = acc[am][an];
                    mma_bf16(d, af[1][am], bf[1][an]);
                    mma_bf16(d, af[1][am], bf[0][an]);
                    mma_bf16(d, af[0][am], bf[1][an]);
                    mma_bf16(d, af[0][am], bf[0][an]);
                }
        }

        // ---- stage chunk j+1 (A from regs), prefetch A chunk j+2 ----
        if (j + 1 < NCHUNK) {
            sts_a((j + 1) & 1, ra);
            if (j + 2 < NCHUNK) ldg_a(j + 2, ra);
            CP_WAIT0();
        }
        __syncthreads();
    }

#pragma unroll
    for (int am = 0; am < 4; am++) {
        int r0 = rowBase + wm * 64 + am * 16 + q;
#pragma unroll
        for (int an = 0; an < 4; an++) {
            int c = colBase + wn * 32 + an * 8 + tg * 2;
            *(float2*)(C + (size_t)r0 * DOUT + c)       = make_float2(acc[am][an][0], acc[am][an][1]);
            *(float2*)(C + (size_t)(r0 + 8) * DOUT + c) = make_float2(acc[am][an][2], acc[am][an][3]);
        }
    }
}

// ---------------------------------------------------------------------------
// LIF flag scan: approx scan; flag lanes with any |mem-1| < FLAG_EPS.
// ---------------------------------------------------------------------------
__global__ __launch_bounds__(256)
void lif_flag_scan_kernel(const float* __restrict__ cur,
                          float* __restrict__ spikes)
{
    const int idx = blockIdx.x * blockDim.x + threadIdx.x;
    const int b = idx >> 9;
    const int d = idx & (DOUT - 1);

    const float* cp = cur    + (size_t)b * TSTEPS * DOUT + d;
    float*       sp = spikes + (size_t)b * TSTEPS * DOUT + d;

    float mem = 0.0f;
    int cnt = 0;
    int flagged = 0;
#pragma unroll 8
    for (int t = 0; t < TSTEPS; t++) {
        float c = cp[(size_t)t * DOUT];
        mem = fmaf(BETA, mem, c);
        flagged |= (fabsf(mem - THRESH) < FLAG_EPS) ? 1 : 0;
        float spk = (mem > THRESH) ? 1.0f : 0.0f;
        mem -= spk * THRESH;
        sp[(size_t)t * DOUT] = spk;
        cnt += (spk > 0.0f) ? 1 : 0;
    }

    if (flagged) {
        cnt = 0;
        int slot = atomicAdd(&g_bcount[b], 1);
        g_bflag_d[b * DOUT + slot] = d;
    }

#pragma unroll
    for (int off = 16; off > 0; off >>= 1)
        cnt += __shfl_down_sync(0xffffffffu, cnt, off);
    if ((threadIdx.x & 31) == 0 && cnt > 0)
        atomicAdd(&g_spike_count, (unsigned long long)cnt);
}

// ---------------------------------------------------------------------------
// Fixup phase A: exact fp32-chain currents for flagged lanes (round-1 order).
// ---------------------------------------------------------------------------
#define XS_STRIDE 36
__global__ __launch_bounds__(256)
void fix_currents_kernel(const float* __restrict__ x,
                         const float* __restrict__ Wm,
                         const float* __restrict__ bias,
                         float* __restrict__ C)
{
    const int b  = blockIdx.y;
    const int t0 = blockIdx.x * 128;
    const int nd = g_bcount[b];
    if (nd == 0) return;

    __shared__ float xs[128 * XS_STRIDE];
    __shared__ float ws[32 * XS_STRIDE];
    __shared__ int   dlist[32];

    const int tid = threadIdx.x;
    const int ts = tid >> 3;
    const int ds = tid & 7;

    for (int dc = 0; dc < nd; dc += 32) {
        __syncthreads();
        if (tid < 32) {
            int j = dc + tid;
            dlist[tid] = g_bflag_d[b * DOUT + ((j < nd) ? j : (nd - 1))];
        }

        float acc[4][4];
#pragma unroll
        for (int i = 0; i < 4; i++)
#pragma unroll
            for (int jj = 0; jj < 4; jj++) acc[i][jj] = 0.0f;

        for (int k0 = 0; k0 < DIN; k0 += 32) {
            __syncthreads();
#pragma unroll
            for (int l = 0; l < 4; l++) {
                int idx = tid + l * 256;
                int r = idx >> 3, c4 = idx & 7;
                float4 v = *(const float4*)(x + ((size_t)b * TSTEPS + t0 + r) * DIN + k0 + c4 * 4);
                *(float4*)(xs + r * XS_STRIDE + c4 * 4) = v;
            }
            {
                int r = tid >> 3, c4 = tid & 7;
                float4 v = *(const float4*)(Wm + (size_t)dlist[r] * DIN + k0 + c4 * 4);
                *(float4*)(ws + r * XS_STRIDE + c4 * 4) = v;
            }
            __syncthreads();

            for (int k = 0; k < 32; k++) {
                float wv[4], xv[4];
#pragma unroll
                for (int jj = 0; jj < 4; jj++) wv[jj] = ws[(ds * 4 + jj) * XS_STRIDE + k];
#pragma unroll
                for (int i = 0; i < 4; i++) xv[i] = xs[(ts * 4 + i) * XS_STRIDE + k];
#pragma unroll
                for (int i = 0; i < 4; i++)
#pragma unroll
                    for (int jj = 0; jj < 4; jj++)
                        acc[i][jj] = fmaf(xv[i], wv[jj], acc[i][jj]);
            }
        }

#pragma unroll
        for (int jj = 0; jj < 4; jj++) {
            int j = dc + ds * 4 + jj;
            if (j < nd) {
                int d = dlist[ds * 4 + jj];
                float bv = bias[d];
#pragma unroll
                for (int i = 0; i < 4; i++) {
                    int t = t0 + ts * 4 + i;
                    C[((size_t)b * TSTEPS + t) * DOUT + d] = acc[i][jj] + bv;
                }
            }
        }
    }
}

// ---------------------------------------------------------------------------
// Fixup phase B: exact rescan of flagged lanes. Parallel strata + MLP unroll.
// ---------------------------------------------------------------------------
__global__ __launch_bounds__(32)
void fix_scan_kernel(const float* __restrict__ cur,
                     float* __restrict__ spikes)
{
    const int b = blockIdx.x;
    const int nd = g_bcount[b];

    for (int slot = blockIdx.y * 32 + threadIdx.x; slot < nd; slot += 8 * 32) {
        const int d = g_bflag_d[b * DOUT + slot];
        const float* cp = cur    + (size_t)b * TSTEPS * DOUT + d;
        float*       sp = spikes + (size_t)b * TSTEPS * DOUT + d;

        float mem = 0.0f;
        int cnt = 0;
#pragma unroll 8
        for (int t = 0; t < TSTEPS; t++) {
            float c = cp[(size_t)t * DOUT];
            mem = fmaf(BETA, mem, c);
            float spk = (mem > THRESH) ? 1.0f : 0.0f;
            mem -= spk * THRESH;
            sp[(size_t)t * DOUT] = spk;
            cnt += (spk > 0.0f) ? 1 : 0;
        }
        atomicAdd(&g_spike_count, (unsigned long long)cnt);
    }
}

__global__ void write_sum_kernel(float* __restrict__ out, int sum_idx) {
    out[sum_idx] = (float)g_spike_count;
}

// ---------------------------------------------------------------------------
extern "C" void kernel_launch(void* const* d_in, const int* in_sizes, int n_in,
                              void* d_out, int out_size)
{
    const float* x    = (const float*)d_in[0];   // [B, T, DIN]
    const float* Wm   = (const float*)d_in[1];   // [DOUT, DIN]
    const float* bias = (const float*)d_in[2];   // [DOUT]
    float* out = (float*)d_out;

    float* currents;
    __nv_bfloat16 *W0, *W1;
    cudaGetSymbolAddress((void**)&currents, g_currents);
    cudaGetSymbolAddress((void**)&W0, g_W0);
    cudaGetSymbolAddress((void**)&W1, g_W1);

    cudaFuncSetAttribute(gemm_bf16x4_kernel,
                         cudaFuncAttributeMaxDynamicSharedMemorySize, SMEM_BYTES);

    zero_kernel<<<1, 128>>>();

    {
        int n4 = DOUT * DIN / 4;
        split2_kernel<<<n4 / 256, 256>>>((const float4*)Wm, (uint2*)W0, (uint2*)W1, n4);
    }

    dim3 grid(DOUT / BN, MROWS / BM);            // (4, 512)
    gemm_bf16x4_kernel<<<grid, 256, SMEM_BYTES>>>(x, W0, W1, bias, currents);

    const int n_lanes = BATCH * DOUT;
    lif_flag_scan_kernel<<<n_lanes / 256, 256>>>(currents, out);

    dim3 fgrid(TSTEPS / 128, BATCH);             // (4, 128)
    fix_currents_kernel<<<fgrid, 256>>>(x, Wm, bias, currents);

    fix_scan_kernel<<<dim3(BATCH, 8), 32>>>(currents, out);

    write_sum_kernel<<<1, 1>>>(out, out_size - 1);
}

// round 11
// speedup vs baseline: 1.6782x; 1.6554x over previous
#include <cuda_runtime.h>
#include <cuda_bf16.h>
#include <stdint.h>

// Problem constants
#define BATCH   128
#define TSTEPS  512
#define DIN     512
#define DOUT    512
#define MROWS   (BATCH * TSTEPS)        // 65536
#define BETA    0.95f
#define THRESH  1.0f
#define FLAG_EPS 5e-4f                  // ~10 sigma of bf16x4 LIF-amplified error

// GEMM tiling
#define BM 128
#define BN 128
#define KC 32
#define NCHUNK (DIN / KC)               // 16
#define SRW 20                          // smem row stride in words (16 data + 4 pad)
#define SUBW (128 * SRW)                // 2560 words per sub-tile
#define STAGEW (4 * SUBW)               // Ahi Alo Whi Wlo
#define SMEM_BYTES (2 * STAGEW * 4)     // 81920

// Persistent scratch (static device globals)
__device__ float g_currents[(size_t)MROWS * DOUT];                 // 128 MB
__device__ __nv_bfloat16 g_W0[(size_t)DOUT * DIN];
__device__ __nv_bfloat16 g_W1[(size_t)DOUT * DIN];
__device__ unsigned long long g_spike_count;
__device__ int g_bcount[BATCH];                  // flagged-lane count per batch
__device__ int g_bflag_d[BATCH * DOUT];          // flagged d list per batch

// ---------------------------------------------------------------------------
__global__ void zero_kernel() {
    if (threadIdx.x == 0) g_spike_count = 0ull;
    if (threadIdx.x < BATCH) g_bcount[threadIdx.x] = 0;
}

// ---------------------------------------------------------------------------
// 2-way bf16 split for W only (1 MB — negligible)
// ---------------------------------------------------------------------------
__global__ __launch_bounds__(256)
void split2_kernel(const float4* __restrict__ src,
                   uint2* __restrict__ o0, uint2* __restrict__ o1, int n4)
{
    int i = blockIdx.x * blockDim.x + threadIdx.x;
    if (i >= n4) return;
    float4 v = src[i];
    float f[4] = {v.x, v.y, v.z, v.w};
    uint16_t h0[4], h1[4];
#pragma unroll
    for (int j = 0; j < 4; j++) {
        __nv_bfloat16 b0 = __float2bfloat16(f[j]);
        __nv_bfloat16 b1 = __float2bfloat16(f[j] - __bfloat162float(b0));
        h0[j] = __bfloat16_as_ushort(b0);
        h1[j] = __bfloat16_as_ushort(b1);
    }
    uint2 p0, p1;
    p0.x = ((uint32_t)h0[1] << 16) | h0[0];
    p0.y = ((uint32_t)h0[3] << 16) | h0[2];
    p1.x = ((uint32_t)h1[1] << 16) | h1[0];
    p1.y = ((uint32_t)h1[3] << 16) | h1[2];
    o0[i] = p0;
    o1[i] = p1;
}

// ---------------------------------------------------------------------------
// cp.async + mma helpers (sm_80 baseline PTX)
// ---------------------------------------------------------------------------
__device__ __forceinline__ uint32_t smem_u32(const void* p) {
    uint32_t a;
    asm("{ .reg .u64 t; cvta.to.shared.u64 t, %1; cvt.u32.u64 %0, t; }" : "=r"(a) : "l"(p));
    return a;
}
#define CP_ASYNC16(dst_u32, src_ptr) \
    asm volatile("cp.async.cg.shared.global [%0], [%1], 16;" :: "r"(dst_u32), "l"(src_ptr) : "memory")
#define CP_COMMIT() asm volatile("cp.async.commit_group;" ::: "memory")
#define CP_WAIT0()  asm volatile("cp.async.wait_group 0;" ::: "memory")

__device__ __forceinline__ void mma_bf16(float* d, const uint32_t* a, const uint32_t* b) {
    asm volatile(
        "mma.sync.aligned.m16n8k16.row.col.f32.bf16.bf16.f32 "
        "{%0,%1,%2,%3}, {%4,%5,%6,%7}, {%8,%9}, {%0,%1,%2,%3};"
        : "+f"(d[0]), "+f"(d[1]), "+f"(d[2]), "+f"(d[3])
        : "r"(a[0]), "r"(a[1]), "r"(a[2]), "r"(a[3]), "r"(b[0]), "r"(b[1]));
}

// convert one float4 to packed bf16 hi/lo pairs
__device__ __forceinline__ void cvt_hi_lo(float4 v, uint2& hi, uint2& lo) {
    float f[4] = {v.x, v.y, v.z, v.w};
    uint16_t h0[4], h1[4];
#pragma unroll
    for (int j = 0; j < 4; j++) {
        __nv_bfloat16 b0 = __float2bfloat16(f[j]);
        __nv_bfloat16 b1 = __float2bfloat16(f[j] - __bfloat162float(b0));
        h0[j] = __bfloat16_as_ushort(b0);
        h1[j] = __bfloat16_as_ushort(b1);
    }
    hi.x = ((uint32_t)h0[1] << 16) | h0[0];
    hi.y = ((uint32_t)h0[3] << 16) | h0[2];
    lo.x = ((uint32_t)h1[1] << 16) | h1[0];
    lo.y = ((uint32_t)h1[3] << 16) | h1[2];
}

// ---------------------------------------------------------------------------
// bf16x4 approx GEMM with fused A split.
// MMA issue order: product-pair-major (16 independent MMAs between
// accumulator reuses) -> no dependent-HMMA latency bubbles.
// ---------------------------------------------------------------------------
__global__ __launch_bounds__(256, 1)
void gemm_bf16x4_kernel(const float* __restrict__ A,
                        const __nv_bfloat16* __restrict__ B0,
                        const __nv_bfloat16* __restrict__ B1,
                        const float* __restrict__ bias,
                        float* __restrict__ C)
{
    extern __shared__ uint32_t smw[];
    const int tid  = threadIdx.x;
    const int wid  = tid >> 5;
    const int lane = tid & 31;
    const int wm = wid & 1;
    const int wn = wid >> 1;
    const int rowBase = blockIdx.y * BM;
    const int colBase = blockIdx.x * BN;
    const int q  = lane >> 2;
    const int tg = lane & 3;

    const uint32_t sb = smem_u32(smw);

    int ar[4], ac4[4];
#pragma unroll
    for (int l = 0; l < 4; l++) {
        int idx = tid + l * 256;
        ar[l]  = idx >> 3;
        ac4[l] = idx & 7;
    }

    float acc[4][4][4];
#pragma unroll
    for (int an = 0; an < 4; an++) {
        int c0 = colBase + wn * 32 + an * 8 + tg * 2;
        float b0 = __ldg(bias + c0), b1 = __ldg(bias + c0 + 1);
#pragma unroll
        for (int am = 0; am < 4; am++) {
            acc[am][an][0] = b0; acc[am][an][1] = b1;
            acc[am][an][2] = b0; acc[am][an][3] = b1;
        }
    }

    auto ldg_a = [&](int j, float4* ra) {
        const int k0 = j * KC;
#pragma unroll
        for (int l = 0; l < 4; l++)
            ra[l] = *(const float4*)(A + (size_t)(rowBase + ar[l]) * DIN + k0 + ac4[l] * 4);
    };
    auto sts_a = [&](int stage, const float4* ra) {
        uint32_t* st = smw + stage * STAGEW;
#pragma unroll
        for (int l = 0; l < 4; l++) {
            uint2 hi, lo;
            cvt_hi_lo(ra[l], hi, lo);
            int off = ar[l] * SRW + ac4[l] * 2;
            *(uint2*)(st + off)        = hi;
            *(uint2*)(st + SUBW + off) = lo;
        }
    };
    auto cpasync_w = [&](int j) {
        const uint32_t st = sb + (uint32_t)((j & 1) * STAGEW + 2 * SUBW) * 4u;
        const int k0 = j * KC;
#pragma unroll
        for (int l = 0; l < 4; l++) {
            int idx = tid + l * 256;
            int sub = idx >> 9;
            int t = idx & 511;
            int r = t >> 2;
            int c16 = t & 3;
            uint32_t doff = (uint32_t)(sub * SUBW + r * SRW + c16 * 4) * 4u;
            const __nv_bfloat16* src = ((sub == 0) ? B0 : B1)
                + (size_t)(colBase + r) * DIN + k0 + c16 * 8;
            CP_ASYNC16(st + doff, src);
        }
        CP_COMMIT();
    };

    float4 ra[4];
    ldg_a(0, ra);
    cpasync_w(0);
    sts_a(0, ra);
    ldg_a(1, ra);
    CP_WAIT0();
    __syncthreads();

    const int aRow = wm * 64 + q;
    const int bRow = wn * 32 + q;

    for (int j = 0; j < NCHUNK; j++) {
        if (j + 1 < NCHUNK) cpasync_w(j + 1);

        const uint32_t* st = smw + (j & 1) * STAGEW;
        const uint32_t* sA = st;
        const uint32_t* sB = st + 2 * SUBW;

#pragma unroll
        for (int s = 0; s < 2; s++) {
            const int kb = s * 8 + tg;
            uint32_t af[2][4][4];
#pragma unroll
            for (int am = 0; am < 4; am++) {
                int r0 = (aRow + am * 16) * SRW + kb;
                int r1 = r0 + 8 * SRW;
#pragma unroll
                for (int p = 0; p < 2; p++) {
                    const uint32_t* a = sA + p * SUBW;
                    af[p][am][0] = a[r0];
                    af[p][am][1] = a[r1];
                    af[p][am][2] = a[r0 + 4];
                    af[p][am][3] = a[r1 + 4];
                }
            }
            uint32_t bf[2][4][2];
#pragma unroll
            for (int an = 0; an < 4; an++) {
                int rb = (bRow + an * 8) * SRW + kb;
#pragma unroll
                for (int p = 0; p < 2; p++) {
                    const uint32_t* b = sB + p * SUBW;
                    bf[p][an][0] = b[rb];
                    bf[p][an][1] = b[rb + 4];
                }
            }
            // product-pair-major: each pass issues 16 independent MMAs
#pragma unroll
            for (int pp = 0; pp < 4; pp++) {
                const int pa = pp >> 1, pb = pp & 1;
#pragma unroll
                for (int am = 0; am < 4; am++)
#pragma unroll
                    for (int an = 0; an < 4; an++)
                        mma_bf16(acc[am][an], af[pa][am], bf[pb][an]);
            }
        }

        if (j + 1 < NCHUNK) {
            sts_a((j + 1) & 1, ra);
            if (j + 2 < NCHUNK) ldg_a(j + 2, ra);
            CP_WAIT0();
        }
        __syncthreads();
    }

#pragma unroll
    for (int am = 0; am < 4; am++) {
        int r0 = rowBase + wm * 64 + am * 16 + q;
#pragma unroll
        for (int an = 0; an < 4; an++) {
            int c = colBase + wn * 32 + an * 8 + tg * 2;
            *(float2*)(C + (size_t)r0 * DOUT + c)       = make_float2(acc[am][an][0], acc[am][an][1]);
            *(float2*)(C + (size_t)(r0 + 8) * DOUT + c) = make_float2(acc[am][an][2], acc[am][an][3]);
        }
    }
}

// ---------------------------------------------------------------------------
// LIF flag scan: approx scan; flag lanes with any |mem-1| < FLAG_EPS.
// ---------------------------------------------------------------------------
__global__ __launch_bounds__(256)
void lif_flag_scan_kernel(const float* __restrict__ cur,
                          float* __restrict__ spikes)
{
    const int idx = blockIdx.x * blockDim.x + threadIdx.x;
    const int b = idx >> 9;
    const int d = idx & (DOUT - 1);

    const float* cp = cur    + (size_t)b * TSTEPS * DOUT + d;
    float*       sp = spikes + (size_t)b * TSTEPS * DOUT + d;

    float mem = 0.0f;
    int cnt = 0;
    int flagged = 0;
#pragma unroll 8
    for (int t = 0; t < TSTEPS; t++) {
        float c = cp[(size_t)t * DOUT];
        mem = fmaf(BETA, mem, c);
        flagged |= (fabsf(mem - THRESH) < FLAG_EPS) ? 1 : 0;
        float spk = (mem > THRESH) ? 1.0f : 0.0f;
        mem -= spk * THRESH;
        sp[(size_t)t * DOUT] = spk;
        cnt += (spk > 0.0f) ? 1 : 0;
    }

    if (flagged) {
        cnt = 0;
        int slot = atomicAdd(&g_bcount[b], 1);
        g_bflag_d[b * DOUT + slot] = d;
    }

#pragma unroll
    for (int off = 16; off > 0; off >>= 1)
        cnt += __shfl_down_sync(0xffffffffu, cnt, off);
    if ((threadIdx.x & 31) == 0 && cnt > 0)
        atomicAdd(&g_spike_count, (unsigned long long)cnt);
}

// ---------------------------------------------------------------------------
// Fixup phase A: exact fp32-chain currents for flagged lanes.
// Grid (t-tiles, B, ZC): flagged-d chunks parallelized over blockIdx.z.
// ---------------------------------------------------------------------------
#define XS_STRIDE 36
#define ZC 4
__global__ __launch_bounds__(256)
void fix_currents_kernel(const float* __restrict__ x,
                         const float* __restrict__ Wm,
                         const float* __restrict__ bias,
                         float* __restrict__ C)
{
    const int b  = blockIdx.y;
    const int t0 = blockIdx.x * 128;
    const int nd = g_bcount[b];
    if ((int)(blockIdx.z * 32) >= nd) return;

    __shared__ float xs[128 * XS_STRIDE];
    __shared__ float ws[32 * XS_STRIDE];
    __shared__ int   dlist[32];

    const int tid = threadIdx.x;
    const int ts = tid >> 3;
    const int ds = tid & 7;

    for (int dc = blockIdx.z * 32; dc < nd; dc += ZC * 32) {
        __syncthreads();
        if (tid < 32) {
            int j = dc + tid;
            dlist[tid] = g_bflag_d[b * DOUT + ((j < nd) ? j : (nd - 1))];
        }

        float acc[4][4];
#pragma unroll
        for (int i = 0; i < 4; i++)
#pragma unroll
            for (int jj = 0; jj < 4; jj++) acc[i][jj] = 0.0f;

        for (int k0 = 0; k0 < DIN; k0 += 32) {
            __syncthreads();
#pragma unroll
            for (int l = 0; l < 4; l++) {
                int idx = tid + l * 256;
                int r = idx >> 3, c4 = idx & 7;
                float4 v = *(const float4*)(x + ((size_t)b * TSTEPS + t0 + r) * DIN + k0 + c4 * 4);
                *(float4*)(xs + r * XS_STRIDE + c4 * 4) = v;
            }
            {
                int r = tid >> 3, c4 = tid & 7;
                float4 v = *(const float4*)(Wm + (size_t)dlist[r] * DIN + k0 + c4 * 4);
                *(float4*)(ws + r * XS_STRIDE + c4 * 4) = v;
            }
            __syncthreads();

            for (int k = 0; k < 32; k++) {
                float wv[4], xv[4];
#pragma unroll
                for (int jj = 0; jj < 4; jj++) wv[jj] = ws[(ds * 4 + jj) * XS_STRIDE + k];
#pragma unroll
                for (int i = 0; i < 4; i++) xv[i] = xs[(ts * 4 + i) * XS_STRIDE + k];
#pragma unroll
                for (int i = 0; i < 4; i++)
#pragma unroll
                    for (int jj = 0; jj < 4; jj++)
                        acc[i][jj] = fmaf(xv[i], wv[jj], acc[i][jj]);
            }
        }

#pragma unroll
        for (int jj = 0; jj < 4; jj++) {
            int j = dc + ds * 4 + jj;
            if (j < nd) {
                int d = dlist[ds * 4 + jj];
                float bv = bias[d];
#pragma unroll
                for (int i = 0; i < 4; i++) {
                    int t = t0 + ts * 4 + i;
                    C[((size_t)b * TSTEPS + t) * DOUT + d] = acc[i][jj] + bv;
                }
            }
        }
    }
}

// ---------------------------------------------------------------------------
// Fixup phase B: exact rescan of flagged lanes.
// ---------------------------------------------------------------------------
__global__ __launch_bounds__(32)
void fix_scan_kernel(const float* __restrict__ cur,
                     float* __restrict__ spikes)
{
    const int b = blockIdx.x;
    const int nd = g_bcount[b];

    for (int slot = blockIdx.y * 32 + threadIdx.x; slot < nd; slot += 8 * 32) {
        const int d = g_bflag_d[b * DOUT + slot];
        const float* cp = cur    + (size_t)b * TSTEPS * DOUT + d;
        float*       sp = spikes + (size_t)b * TSTEPS * DOUT + d;

        float mem = 0.0f;
        int cnt = 0;
#pragma unroll 8
        for (int t = 0; t < TSTEPS; t++) {
            float c = cp[(size_t)t * DOUT];
            mem = fmaf(BETA, mem, c);
            float spk = (mem > THRESH) ? 1.0f : 0.0f;
            mem -= spk * THRESH;
            sp[(size_t)t * DOUT] = spk;
            cnt += (spk > 0.0f) ? 1 : 0;
        }
        atomicAdd(&g_spike_count, (unsigned long long)cnt);
    }
}

__global__ void write_sum_kernel(float* __restrict__ out, int sum_idx) {
    out[sum_idx] = (float)g_spike_count;
}

// ---------------------------------------------------------------------------
extern "C" void kernel_launch(void* const* d_in, const int* in_sizes, int n_in,
                              void* d_out, int out_size)
{
    const float* x    = (const float*)d_in[0];   // [B, T, DIN]
    const float* Wm   = (const float*)d_in[1];   // [DOUT, DIN]
    const float* bias = (const float*)d_in[2];   // [DOUT]
    float* out = (float*)d_out;

    float* currents;
    __nv_bfloat16 *W0, *W1;
    cudaGetSymbolAddress((void**)&currents, g_currents);
    cudaGetSymbolAddress((void**)&W0, g_W0);
    cudaGetSymbolAddress((void**)&W1, g_W1);

    cudaFuncSetAttribute(gemm_bf16x4_kernel,
                         cudaFuncAttributeMaxDynamicSharedMemorySize, SMEM_BYTES);

    zero_kernel<<<1, 128>>>();

    {
        int n4 = DOUT * DIN / 4;
        split2_kernel<<<n4 / 256, 256>>>((const float4*)Wm, (uint2*)W0, (uint2*)W1, n4);
    }

    dim3 grid(DOUT / BN, MROWS / BM);            // (4, 512)
    gemm_bf16x4_kernel<<<grid, 256, SMEM_BYTES>>>(x, W0, W1, bias, currents);

    const int n_lanes = BATCH * DOUT;
    lif_flag_scan_kernel<<<n_lanes / 256, 256>>>(currents, out);

    dim3 fgrid(TSTEPS / 128, BATCH, ZC);         // (4, 128, 4)
    fix_currents_kernel<<<fgrid, 256>>>(x, Wm, bias, currents);

    fix_scan_kernel<<<dim3(BATCH, 8), 32>>>(currents, out);

    write_sum_kernel<<<1, 1>>>(out, out_size - 1);
}